// round 16
// baseline (speedup 1.0000x reference)
#include <cuda_runtime.h>
#include <math.h>
#include <stdint.h>

#define NIMG   8
#define KSEL   4768
#define NWL    16          /* per-level mask words (1024/64) */
#define POSTN  1000
#define CANDCAP 16384

typedef unsigned long long u64;
typedef unsigned int u32;
typedef unsigned short u16;

__device__ __constant__ int c_FEAT[5]   = {256, 128, 64, 32, 16};
__device__ __constant__ int c_KLVL[5]   = {1000, 1000, 1000, 1000, 768};
__device__ __constant__ int c_SELOFF[5] = {0, 1000, 2000, 3000, 4000};
__device__ __constant__ int c_LOFF[5]   = {0, 196608, 245760, 258048, 261120};

struct KArgs {
    const float* obj[5];
    const float* del[5];
    const float* anc;
};

// ------------- static device scratch (no allocation) -------------
__device__ u32    g_hist[40][256];             // radix histograms (re-zeroed by selfin)
__device__ u32    g_cntC[40];                  // candidate counts (re-zeroed by selfin)
__device__ u64    g_cand[40][CANDCAP];         // sel candidate scratch
__device__ u64    g_key[NIMG][KSEL];           // composite sort keys (pos-indexed)
__device__ float4 g_px[NIMG][KSEL];            // pos-indexed clipped boxes
// per-(img,lvl) level-local offset boxes / area / validity / keep bits
__device__ float4 g_lbox[40][1024];            // offset boxes (x1,y1,x2,y2)
__device__ float  g_lar[40][1024];
__device__ u64    g_lvb[40][NWL];              // valid bits (written whole by selfin)
__device__ u64    g_keepbits[40][NWL];         // NMS keep flags per level
__device__ u64    g_lmask[40][1024][NWL];      // per-level suppression matrix

// monotone float->uint key (ascending float == ascending uint)
__device__ __forceinline__ u32 fkey(float f) {
    u32 b = __float_as_uint(f);
    return (b & 0x80000000u) ? ~b : (b | 0x80000000u);
}
// exact inverse of fkey
__device__ __forceinline__ float fkey_inv(u32 k) {
    return (k & 0x80000000u) ? __uint_as_float(k & 0x7FFFFFFFu)
                             : __uint_as_float(~k);
}

// ================= stage A: chip-wide top-8-bit histogram =================
__global__ __launch_bounds__(256) void histA_kernel(KArgs A) {
    int pair = blockIdx.x; int img = pair / 5, lvl = pair % 5;
    int F = c_FEAT[lvl]; int HW = F * F; int n = HW * 3;
    const float* base = A.obj[lvl] + (size_t)img * 3 * HW;
    int lane = threadIdx.x & 31;
    __shared__ u32 h[256];
    h[threadIdx.x] = 0;
    __syncthreads();
    int stride = gridDim.y * 256;
    for (int t = blockIdx.y * 256 + threadIdx.x; t < n; t += stride) {
        u32 d = fkey(base[t]) >> 24;
        u32 peers = __match_any_sync(0xFFFFFFFFu, d);
        if (lane == (__ffs(peers) - 1))
            atomicAdd(&h[d], (u32)__popc(peers));
    }
    __syncthreads();
    u32 v = h[threadIdx.x];
    if (v) atomicAdd(&g_hist[pair][threadIdx.x], v);
}

// ================= stage B: candidate compaction (inline cut recompute) =========
__global__ __launch_bounds__(256) void compact_kernel(KArgs A) {
    int pair = blockIdx.x; int img = pair / 5, lvl = pair % 5;
    int F = c_FEAT[lvl]; int HW = F * F; int n = HW * 3; int k = c_KLVL[lvl];
    const float* base = A.obj[lvl] + (size_t)img * 3 * HW;
    u64* cand = g_cand[pair];
    int lane = threadIdx.x & 31;

    __shared__ u32 h[256];
    __shared__ u32 sh_d1;
    h[threadIdx.x] = g_hist[pair][threadIdx.x];
    __syncthreads();
    if (threadIdx.x == 0) {
        u32 sum = 0; int d = 0;
        for (d = 255; d >= 0; d--) {
            u32 s2 = sum + h[d];
            if (s2 >= (u32)k) break;
            sum = s2;
        }
        sh_d1 = (u32)d;
    }
    __syncthreads();
    u32 d1 = sh_d1;

    int stride = gridDim.y * 256;
    for (int t = blockIdx.y * 256 + threadIdx.x; t < n; t += stride) {
        u32 key = fkey(base[t]);
        bool pred = ((key >> 24) >= d1);
        u32 bal = __ballot_sync(0xFFFFFFFFu, pred);
        u32 base_s = 0;
        if (bal) {
            int leader = __ffs(bal) - 1;
            if (lane == leader) base_s = atomicAdd(&g_cntC[pair], (u32)__popc(bal));
            base_s = __shfl_sync(0xFFFFFFFFu, base_s, leader);
        }
        if (pred) {
            u32 s = base_s + __popc(bal & ((1u << lane) - 1u));
            if (s < CANDCAP) {
                int a = t / HW; int hw = t - a * HW;
                u32 local = (u32)hw * 3u + (u32)a;     // [H,W,A] flatten index
                cand[s] = ((u64)key << 32) | (u32)(~local);
            }
        }
    }
}

// ===== stage C: radix 3-5 + G-bitonic + E-counting-rank + fused decode =====
__global__ __launch_bounds__(1024) void selfin_kernel(KArgs A) {
    int pair = blockIdx.x; int img = pair / 5, lvl = pair % 5;
    int k = c_KLVL[lvl];
    int tid = threadIdx.x;
    u64* cand = g_cand[pair];
    u32 m = g_cntC[pair]; if (m > CANDCAP) m = CANDCAP;

    __shared__ u32 hist[256];
    __shared__ u32 sh_prefix, sh_kr;
    __shared__ u64 bufG[1024];
    __shared__ u64 bufE[1024];
    __shared__ u64 sortedE[1024];
    __shared__ u32 cntG, cntE;
    __shared__ u64 vb[NWL];

    // ---- inline cut from g_hist ----
    if (tid < 256) hist[tid] = g_hist[pair][tid];
    if (tid < NWL) vb[tid] = 0ull;
    if (tid == 0) { cntG = 0; cntE = 0; }
    __syncthreads();
    if (tid == 0) {
        u32 sum = 0; int d = 0;
        for (d = 255; d >= 0; d--) {
            u32 s2 = sum + hist[d];
            if (s2 >= (u32)k) { sh_kr = (u32)k - sum; break; }
            sum = s2;
        }
        sh_prefix = (u32)d << 24;
    }
    __syncthreads();

    // ---- radix passes 3-5 on candidate buffer ----
    for (int b = 2; b >= 0; b--) {
        for (int t = tid; t < 256; t += 1024) hist[t] = 0;
        __syncthreads();
        u32 pref = sh_prefix;
        u32 maskH = 0xFFFFFFFFu << (8 * (b + 1));
        for (int t = tid; t < (int)m; t += 1024) {
            u32 key = (u32)(cand[t] >> 32);
            if ((key & maskH) == (pref & maskH))
                atomicAdd(&hist[(key >> (8 * b)) & 255u], 1u);
        }
        __syncthreads();
        if (tid == 0) {
            u32 kr = sh_kr, sum = 0; int d = 0;
            for (d = 255; d >= 0; d--) {
                u32 s2 = sum + hist[d];
                if (s2 >= kr) { sh_kr = kr - sum; break; }
                sum = s2;
            }
            sh_prefix = pref | ((u32)d << (8 * b));
        }
        __syncthreads();
    }
    u32 Kth = sh_prefix;

    // ---- compact: G (> Kth, nG <= k-1 < 1024) and E (== Kth) ----
    bufG[tid] = 0ull; bufE[tid] = 0ull;
    __syncthreads();
    for (int t = tid; t < (int)m; t += 1024) {
        u64 comp = cand[t];
        u32 key = (u32)(comp >> 32);
        if (key > Kth)       { u32 s = atomicAdd(&cntG, 1u); if (s < 1024u) bufG[s] = comp; }
        else if (key == Kth) { u32 s = atomicAdd(&cntE, 1u); if (s < 1024u) bufE[s] = comp; }
    }
    __syncthreads();
    u32 nG = cntG;                         // exact (< k <= 1000)
    u32 nE = cntE; if (nE > 1024u) nE = 1024u;

    // ---- descending 1024-bitonic on G half only ----
    for (int kk = 2; kk <= 1024; kk <<= 1)
        for (int j = kk >> 1; j > 0; j >>= 1) {
            __syncthreads();
            int ixj = tid ^ j;
            if (ixj > tid) {
                u64 a = bufG[tid], bb = bufG[ixj];
                bool desc = ((tid & kk) == 0);
                if (desc ? (a < bb) : (a > bb)) { bufG[tid] = bb; bufG[ixj] = a; }
            }
        }
    __syncthreads();

    // ---- E half: identical keys, order by comp desc (= index asc); counting rank ----
    if (tid < (int)nE) {
        u64 e = bufE[tid];
        int r = 0;
        for (int j = 0; j < (int)nE; j++) r += (bufE[j] > e);
        sortedE[r] = e;
    }
    __syncthreads();

    // ---- fused decode: thread r = level rank r ----
    if (tid < k) {
        int r = tid;
        u64 comp = (r < (int)nG) ? bufG[r] : sortedE[r - (int)nG];
        u32 keyhi = (u32)(comp >> 32);
        u32 local = ~(u32)comp;
        int loff = c_LOFF[lvl]; int F = c_FEAT[lvl]; int HW = F * F;
        int a = (int)(local % 3u); int hw = (int)(local / 3u);
        int h = hw / F; int w = hw - h * F;
        u32 gidx = (u32)loff + local;
        int pos = c_SELOFF[lvl] + r;

        float logit = fkey_inv(keyhi);
        float score = __fdiv_rn(1.0f, __fadd_rn(1.0f, expf(-logit)));

        const float* dp = A.del[lvl] + ((size_t)img * 12 + a * 4) * HW + (size_t)h * F + w;
        float dx  = dp[0];
        float dy  = dp[(size_t)HW];
        float dwv = dp[2 * (size_t)HW];
        float dhv = dp[3 * (size_t)HW];
        const float* an = A.anc + 4 * (size_t)gidx;
        float ax1 = an[0], ay1 = an[1], ax2 = an[2], ay2 = an[3];
        float aw = __fsub_rn(ax2, ax1);
        float ah = __fsub_rn(ay2, ay1);
        float cx = __fadd_rn(ax1, __fmul_rn(0.5f, aw));
        float cy = __fadd_rn(ay1, __fmul_rn(0.5f, ah));
        const float CLIP = 4.135166556742356f;
        float dwc = fminf(dwv, CLIP);
        float dhc = fminf(dhv, CLIP);
        float pcx = __fadd_rn(__fmul_rn(dx, aw), cx);
        float pcy = __fadd_rn(__fmul_rn(dy, ah), cy);
        float pw  = __fmul_rn(expf(dwc), aw);
        float ph  = __fmul_rn(expf(dhc), ah);
        float x1 = __fsub_rn(pcx, __fmul_rn(0.5f, pw));
        float y1 = __fsub_rn(pcy, __fmul_rn(0.5f, ph));
        float x2 = __fadd_rn(pcx, __fmul_rn(0.5f, pw));
        float y2 = __fadd_rn(pcy, __fmul_rn(0.5f, ph));
        x1 = fminf(fmaxf(x1, 0.0f), 1024.0f);
        y1 = fminf(fmaxf(y1, 0.0f), 1024.0f);
        x2 = fminf(fmaxf(x2, 0.0f), 1024.0f);
        y2 = fminf(fmaxf(y2, 0.0f), 1024.0f);

        bool valid = (__fsub_rn(x2, x1) >= 1e-3f) && (__fsub_rn(y2, y1) >= 1e-3f);
        g_px[img][pos] = make_float4(x1, y1, x2, y2);
        float sc = valid ? score : -1.0f;
        g_key[img][pos] = ((u64)fkey(sc) << 32) | (u32)(~(u32)pos);

        float ofs = (float)lvl * 1025.0f;
        float ox1 = __fadd_rn(x1, ofs), oy1 = __fadd_rn(y1, ofs);
        float ox2 = __fadd_rn(x2, ofs), oy2 = __fadd_rn(y2, ofs);
        g_lbox[pair][r] = make_float4(ox1, oy1, ox2, oy2);
        g_lar[pair][r] = __fmul_rn(__fsub_rn(ox2, ox1), __fsub_rn(oy2, oy1));
        if (valid) atomicOr(&vb[r >> 6], 1ull << (r & 63));
    }
    __syncthreads();
    if (tid < NWL) g_lvb[pair][tid] = vb[tid];

    // ---- reset per-replay state ----
    if (tid < 256) g_hist[pair][tid] = 0;
    if (tid == 0) g_cntC[pair] = 0;
}

// ================= per-level IoU suppression matrix (upper tri, specialized) ======
#define IOU_BIT(jj)                                                            \
    {                                                                          \
        float4 cb = cbox[jj];                                                  \
        float ltx = fmaxf(ix1, cb.x);                                          \
        float lty = fmaxf(iy1, cb.y);                                          \
        float rbx = fminf(ix2, cb.z);                                          \
        float rby = fminf(iy2, cb.w);                                          \
        float w = fmaxf(__fsub_rn(rbx, ltx), 0.0f);                            \
        float h = fmaxf(__fsub_rn(rby, lty), 0.0f);                            \
        float inter = __fmul_rn(w, h);                                         \
        float den = __fadd_rn(__fsub_rn(__fadd_rn(ai, car[jj]), inter), 1e-9f);\
        bool sup;                                                              \
        if (inter > __fmul_rn(den, 0.703125f))       sup = true;               \
        else if (inter < __fmul_rn(den, 0.6953125f)) sup = false;              \
        else sup = (__fdiv_rn(inter, den) > 0.7f);                             \
        if (sup) word |= (1ull << (jj));                                       \
    }

__global__ __launch_bounds__(256) void lmask_kernel() {
    int pair = blockIdx.z; int lvl = pair % 5;
    int kl = c_KLVL[lvl];
    int colb = blockIdx.x, rowb4 = blockIdx.y;
    if (rowb4 * 4 > colb) return;            // whole block lower triangle
    int tid = threadIdx.x;
    int sub = tid >> 6, lane = tid & 63;
    int rowb = rowb4 * 4 + sub;

    __shared__ float4 cbox[64];
    __shared__ float car[64];
    int j0 = colb * 64;
    if (tid < 64) {
        int j = j0 + tid;
        if (j < kl) {
            cbox[tid] = g_lbox[pair][j];
            car[tid]  = g_lar[pair][j];
        } else {
            cbox[tid] = make_float4(0.f, 0.f, 0.f, 0.f);
            car[tid] = 0.f;
        }
    }
    __syncthreads();
    if (rowb > colb) return;                 // this row-tile below diagonal
    int i = rowb * 64 + lane;
    u64 word = 0ull;
    if (i < kl) {
        float4 rb = g_lbox[pair][i];
        float ix1 = rb.x, iy1 = rb.y, ix2 = rb.z, iy2 = rb.w;
        float ai = g_lar[pair][i];
        int jmax = kl - j0; if (jmax > 64) jmax = 64;   // may be <=0 for padded cols
        if (rowb < colb && jmax == 64) {
            // interior tile: every j in-range and j > i — no per-iter conditionals
            #pragma unroll 16
            for (int jj = 0; jj < 64; jj++) IOU_BIT(jj);
        } else if (rowb == colb) {
            // diagonal tile: start at lane+1, bound by jmax
            for (int jj = lane + 1; jj < jmax; jj++) IOU_BIT(jj);
        } else {
            // ragged right edge (rowb < colb, jmax < 64)
            for (int jj = 0; jj < jmax; jj++) IOU_BIT(jj);
        }
    }
    if (i < 1024) g_lmask[pair][i][colb] = word;  // zeros beyond kl keep eager ORs safe
}

// ================= per-level greedy NMS (40 independent blocks) =================
__global__ __launch_bounds__(256) void lnms_kernel() {
    int pair = blockIdx.x; int lvl = pair % 5;
    int kl = c_KLVL[lvl];
    int nc = (kl + 63) >> 6;
    int tid = threadIdx.x;
    __shared__ u64 remv[NWL];
    __shared__ u64 smask[64];
    __shared__ u64 kb[NWL];
    __shared__ int skept[64];
    __shared__ int snk;
    if (tid < NWL) { remv[tid] = 0ull; kb[tid] = 0ull; }
    __syncthreads();

    for (int c = 0; c < nc; c++) {
        int i0 = c * 64;
        if (tid < 64) {
            int i = i0 + tid;
            smask[tid] = (i < kl) ? g_lmask[pair][i][c] : 0ull;
        }
        __syncthreads();
        if (tid == 0) {
            u64 alive = g_lvb[pair][c] & ~remv[c];
            int nk = 0; u64 kw = 0ull;
            while (alive) {
                int b = __ffsll((long long)alive) - 1;
                skept[nk++] = i0 + b; kw |= (1ull << b);
                alive &= ~smask[b];              // row has only j>i bits
                alive &= ~(1ull << b);
            }
            snk = nk; kb[c] = kw;
        }
        __syncthreads();
        int nk = snk, nw = nc - 1 - c;
        int total = nk * nw;
        for (int p = tid; p < total; p += 256) {
            int kk = p / nw; int w = c + 1 + (p - kk * nw);
            u64 mm = g_lmask[pair][skept[kk]][w];
            if (mm) atomicOr(&remv[w], mm);
        }
        __syncthreads();
    }
    if (tid < NWL) g_keepbits[pair][tid] = kb[tid];
}

// ========== rank kept boxes only + output (fused, per image) ==========
// Kept boxes per level form a score-descending list (subsequence of the sorted
// top-k). Output rank of a kept box = index in own level's kept list + count of
// strictly-greater keys in the other 4 kept lists (binary search; keys unique).
__global__ __launch_bounds__(1024) void rankfin_kernel(float* __restrict__ out) {
    int img = blockIdx.x;
    int tid = threadIdx.x;

    __shared__ u64 keptKeys[KSEL];
    __shared__ u16 keptPos[KSEL];
    __shared__ u64 kb[5][NWL];
    __shared__ u32 pc[5][NWL];
    __shared__ u32 start[6];

    // load keepbits + popcounts
    if (tid < 80) {
        int l = tid >> 4, w = tid & 15;
        u64 v = g_keepbits[img * 5 + l][w];
        kb[l][w] = v;
        pc[l][w] = (u32)__popcll(v);
    }
    __syncthreads();
    if (tid == 0) {
        u32 s = 0;
        for (int l = 0; l < 5; l++) {
            start[l] = s;
            for (int w = 0; w < NWL; w++) s += pc[l][w];
        }
        start[5] = s;
    }
    __syncthreads();
    u32 totKept = start[5];

    // compact kept keys/positions (one thread per (level, word))
    if (tid < 80) {
        int l = tid >> 4, w = tid & 15;
        u32 base = start[l];
        for (int w2 = 0; w2 < w; w2++) base += pc[l][w2];
        u64 bits = kb[l][w];
        int seloff = c_SELOFF[l];
        int rbase = w * 64;
        while (bits) {
            int b = __ffsll((long long)bits) - 1;
            bits &= bits - 1ull;
            int pos = seloff + rbase + b;
            keptKeys[base] = g_key[img][pos];
            keptPos[base]  = (u16)pos;
            base++;
        }
    }
    __syncthreads();

    // rank each kept element among kept; write output
    for (u32 e = tid; e < totKept; e += 1024) {
        int lvl = 0;
        while (lvl < 4 && e >= start[lvl + 1]) lvl++;
        u64 mykey = keptKeys[e];
        u32 r = e - start[lvl];
        #pragma unroll
        for (int l2 = 0; l2 < 5; l2++) {
            if (l2 == lvl) continue;
            u32 lo = start[l2], hi = start[l2 + 1];
            u32 st = lo;
            while (lo < hi) {
                u32 mid = (lo + hi) >> 1;
                if (keptKeys[mid] > mykey) lo = mid + 1; else hi = mid;
            }
            r += lo - st;
        }
        if (r < POSTN) {
            float4 b = g_px[img][keptPos[e]];
            float* o = out + ((size_t)img * POSTN + r) * 4;
            o[0] = b.x; o[1] = b.y; o[2] = b.z; o[3] = b.w;
        }
    }
    __syncthreads();
    int tot = (int)totKept; if (tot > POSTN) tot = POSTN;
    for (int idx = tot * 4 + tid; idx < POSTN * 4; idx += 1024)
        out[(size_t)img * POSTN * 4 + idx] = 0.0f;
}

// ================= host launcher =================
extern "C" void kernel_launch(void* const* d_in, const int* in_sizes, int n_in,
                              void* d_out, int out_size) {
    KArgs A;
    bool interleaved = (in_sizes[1] == 6291456);
    for (int i = 0; i < 5; i++) {
        A.obj[i] = (const float*)d_in[interleaved ? 2 * i : i];
        A.del[i] = (const float*)d_in[interleaved ? 2 * i + 1 : 5 + i];
    }
    A.anc = (const float*)d_in[10];
    float* out = (float*)d_out;

    histA_kernel<<<dim3(40, 16), 256>>>(A);
    compact_kernel<<<dim3(40, 16), 256>>>(A);
    selfin_kernel<<<40, 1024>>>(A);
    lmask_kernel<<<dim3(NWL, 4, 40), 256>>>();
    lnms_kernel<<<40, 256>>>();
    rankfin_kernel<<<NIMG, 1024>>>(out);
}

// round 17
// speedup vs baseline: 1.5390x; 1.5390x over previous
#include <cuda_runtime.h>
#include <math.h>
#include <stdint.h>

#define NIMG   8
#define KSEL   4768
#define NWORDS 75          /* ceil(4768/64) global-rank words */
#define NWL    16          /* per-level mask words (1024/64) */
#define POSTN  1000
#define CANDCAP 16384

typedef unsigned long long u64;
typedef unsigned int u32;

__device__ __constant__ int c_FEAT[5]   = {256, 128, 64, 32, 16};
__device__ __constant__ int c_KLVL[5]   = {1000, 1000, 1000, 1000, 768};
__device__ __constant__ int c_SELOFF[5] = {0, 1000, 2000, 3000, 4000};
__device__ __constant__ int c_LOFF[5]   = {0, 196608, 245760, 258048, 261120};

struct KArgs {
    const float* obj[5];
    const float* del[5];
    const float* anc;
};

// ------------- static device scratch (no allocation) -------------
__device__ u32    g_hist[40][256];             // radix histograms (re-zeroed by selfin)
__device__ u32    g_cntC[40];                  // candidate counts (re-zeroed by selfin)
__device__ u64    g_cand[40][CANDCAP];         // sel candidate scratch
__device__ u64    g_key[NIMG][KSEL];           // composite sort keys (pos-indexed)
__device__ float4 g_px[NIMG][KSEL];            // pos-indexed clipped boxes
// per-(img,lvl) level-local offset boxes / area / validity / keep bits
__device__ float  g_lx1[40][1024], g_ly1[40][1024], g_lx2[40][1024], g_ly2[40][1024];
__device__ float  g_lar[40][1024];
__device__ u64    g_lvb[40][NWL];              // valid bits (written whole by selfin)
__device__ u64    g_keepbits[40][NWL];         // NMS keep flags per level
__device__ u64    g_lmask[40][1024][NWL];      // per-level suppression matrix

// monotone float->uint key (ascending float == ascending uint)
__device__ __forceinline__ u32 fkey(float f) {
    u32 b = __float_as_uint(f);
    return (b & 0x80000000u) ? ~b : (b | 0x80000000u);
}
// exact inverse of fkey
__device__ __forceinline__ float fkey_inv(u32 k) {
    return (k & 0x80000000u) ? __uint_as_float(k & 0x7FFFFFFFu)
                             : __uint_as_float(~k);
}

// ================= stage A: chip-wide top-8-bit histogram =================
__global__ __launch_bounds__(256) void histA_kernel(KArgs A) {
    int pair = blockIdx.x; int img = pair / 5, lvl = pair % 5;
    int F = c_FEAT[lvl]; int HW = F * F; int n = HW * 3;
    const float* base = A.obj[lvl] + (size_t)img * 3 * HW;
    int lane = threadIdx.x & 31;
    __shared__ u32 h[256];
    h[threadIdx.x] = 0;
    __syncthreads();
    int stride = gridDim.y * 256;
    for (int t = blockIdx.y * 256 + threadIdx.x; t < n; t += stride) {
        u32 d = fkey(base[t]) >> 24;
        u32 peers = __match_any_sync(0xFFFFFFFFu, d);
        if (lane == (__ffs(peers) - 1))
            atomicAdd(&h[d], (u32)__popc(peers));
    }
    __syncthreads();
    u32 v = h[threadIdx.x];
    if (v) atomicAdd(&g_hist[pair][threadIdx.x], v);
}

// ================= stage B: candidate compaction (inline cut recompute) =========
__global__ __launch_bounds__(256) void compact_kernel(KArgs A) {
    int pair = blockIdx.x; int img = pair / 5, lvl = pair % 5;
    int F = c_FEAT[lvl]; int HW = F * F; int n = HW * 3; int k = c_KLVL[lvl];
    const float* base = A.obj[lvl] + (size_t)img * 3 * HW;
    u64* cand = g_cand[pair];
    int lane = threadIdx.x & 31;

    __shared__ u32 h[256];
    __shared__ u32 sh_d1;
    h[threadIdx.x] = g_hist[pair][threadIdx.x];
    __syncthreads();
    if (threadIdx.x == 0) {
        u32 sum = 0; int d = 0;
        for (d = 255; d >= 0; d--) {
            u32 s2 = sum + h[d];
            if (s2 >= (u32)k) break;
            sum = s2;
        }
        sh_d1 = (u32)d;
    }
    __syncthreads();
    u32 d1 = sh_d1;

    int stride = gridDim.y * 256;
    for (int t = blockIdx.y * 256 + threadIdx.x; t < n; t += stride) {
        u32 key = fkey(base[t]);
        bool pred = ((key >> 24) >= d1);
        u32 bal = __ballot_sync(0xFFFFFFFFu, pred);
        u32 base_s = 0;
        if (bal) {
            int leader = __ffs(bal) - 1;
            if (lane == leader) base_s = atomicAdd(&g_cntC[pair], (u32)__popc(bal));
            base_s = __shfl_sync(0xFFFFFFFFu, base_s, leader);
        }
        if (pred) {
            u32 s = base_s + __popc(bal & ((1u << lane) - 1u));
            if (s < CANDCAP) {
                int a = t / HW; int hw = t - a * HW;
                u32 local = (u32)hw * 3u + (u32)a;     // [H,W,A] flatten index
                cand[s] = ((u64)key << 32) | (u32)(~local);
            }
        }
    }
}

// ===== stage C: radix 3-5 + G-bitonic + E-counting-rank + fused decode =====
__global__ __launch_bounds__(1024) void selfin_kernel(KArgs A) {
    int pair = blockIdx.x; int img = pair / 5, lvl = pair % 5;
    int k = c_KLVL[lvl];
    int tid = threadIdx.x;
    u64* cand = g_cand[pair];
    u32 m = g_cntC[pair]; if (m > CANDCAP) m = CANDCAP;

    __shared__ u32 hist[256];
    __shared__ u32 sh_prefix, sh_kr;
    __shared__ u64 bufG[1024];
    __shared__ u64 bufE[1024];
    __shared__ u64 sortedE[1024];
    __shared__ u32 cntG, cntE;
    __shared__ u64 vb[NWL];

    // ---- inline cut from g_hist ----
    if (tid < 256) hist[tid] = g_hist[pair][tid];
    if (tid < NWL) vb[tid] = 0ull;
    if (tid == 0) { cntG = 0; cntE = 0; }
    __syncthreads();
    if (tid == 0) {
        u32 sum = 0; int d = 0;
        for (d = 255; d >= 0; d--) {
            u32 s2 = sum + hist[d];
            if (s2 >= (u32)k) { sh_kr = (u32)k - sum; break; }
            sum = s2;
        }
        sh_prefix = (u32)d << 24;
    }
    __syncthreads();

    // ---- radix passes 3-5 on candidate buffer ----
    for (int b = 2; b >= 0; b--) {
        for (int t = tid; t < 256; t += 1024) hist[t] = 0;
        __syncthreads();
        u32 pref = sh_prefix;
        u32 maskH = 0xFFFFFFFFu << (8 * (b + 1));
        for (int t = tid; t < (int)m; t += 1024) {
            u32 key = (u32)(cand[t] >> 32);
            if ((key & maskH) == (pref & maskH))
                atomicAdd(&hist[(key >> (8 * b)) & 255u], 1u);
        }
        __syncthreads();
        if (tid == 0) {
            u32 kr = sh_kr, sum = 0; int d = 0;
            for (d = 255; d >= 0; d--) {
                u32 s2 = sum + hist[d];
                if (s2 >= kr) { sh_kr = kr - sum; break; }
                sum = s2;
            }
            sh_prefix = pref | ((u32)d << (8 * b));
        }
        __syncthreads();
    }
    u32 Kth = sh_prefix;

    // ---- compact: G (> Kth, nG <= k-1 < 1024) and E (== Kth) ----
    bufG[tid] = 0ull; bufE[tid] = 0ull;
    __syncthreads();
    for (int t = tid; t < (int)m; t += 1024) {
        u64 comp = cand[t];
        u32 key = (u32)(comp >> 32);
        if (key > Kth)       { u32 s = atomicAdd(&cntG, 1u); if (s < 1024u) bufG[s] = comp; }
        else if (key == Kth) { u32 s = atomicAdd(&cntE, 1u); if (s < 1024u) bufE[s] = comp; }
    }
    __syncthreads();
    u32 nG = cntG;                         // exact (< k <= 1000)
    u32 nE = cntE; if (nE > 1024u) nE = 1024u;

    // ---- descending 1024-bitonic on G half only ----
    for (int kk = 2; kk <= 1024; kk <<= 1)
        for (int j = kk >> 1; j > 0; j >>= 1) {
            __syncthreads();
            int ixj = tid ^ j;
            if (ixj > tid) {
                u64 a = bufG[tid], bb = bufG[ixj];
                bool desc = ((tid & kk) == 0);
                if (desc ? (a < bb) : (a > bb)) { bufG[tid] = bb; bufG[ixj] = a; }
            }
        }
    __syncthreads();

    // ---- E half: identical keys, order by comp desc (= index asc); counting rank ----
    if (tid < (int)nE) {
        u64 e = bufE[tid];
        int r = 0;
        for (int j = 0; j < (int)nE; j++) r += (bufE[j] > e);
        sortedE[r] = e;
    }
    __syncthreads();

    // ---- fused decode: thread r = level rank r ----
    if (tid < k) {
        int r = tid;
        u64 comp = (r < (int)nG) ? bufG[r] : sortedE[r - (int)nG];
        u32 keyhi = (u32)(comp >> 32);
        u32 local = ~(u32)comp;
        int loff = c_LOFF[lvl]; int F = c_FEAT[lvl]; int HW = F * F;
        int a = (int)(local % 3u); int hw = (int)(local / 3u);
        int h = hw / F; int w = hw - h * F;
        u32 gidx = (u32)loff + local;
        int pos = c_SELOFF[lvl] + r;

        float logit = fkey_inv(keyhi);
        float score = __fdiv_rn(1.0f, __fadd_rn(1.0f, expf(-logit)));

        const float* dp = A.del[lvl] + ((size_t)img * 12 + a * 4) * HW + (size_t)h * F + w;
        float dx  = dp[0];
        float dy  = dp[(size_t)HW];
        float dwv = dp[2 * (size_t)HW];
        float dhv = dp[3 * (size_t)HW];
        const float* an = A.anc + 4 * (size_t)gidx;
        float ax1 = an[0], ay1 = an[1], ax2 = an[2], ay2 = an[3];
        float aw = __fsub_rn(ax2, ax1);
        float ah = __fsub_rn(ay2, ay1);
        float cx = __fadd_rn(ax1, __fmul_rn(0.5f, aw));
        float cy = __fadd_rn(ay1, __fmul_rn(0.5f, ah));
        const float CLIP = 4.135166556742356f;
        float dwc = fminf(dwv, CLIP);
        float dhc = fminf(dhv, CLIP);
        float pcx = __fadd_rn(__fmul_rn(dx, aw), cx);
        float pcy = __fadd_rn(__fmul_rn(dy, ah), cy);
        float pw  = __fmul_rn(expf(dwc), aw);
        float ph  = __fmul_rn(expf(dhc), ah);
        float x1 = __fsub_rn(pcx, __fmul_rn(0.5f, pw));
        float y1 = __fsub_rn(pcy, __fmul_rn(0.5f, ph));
        float x2 = __fadd_rn(pcx, __fmul_rn(0.5f, pw));
        float y2 = __fadd_rn(pcy, __fmul_rn(0.5f, ph));
        x1 = fminf(fmaxf(x1, 0.0f), 1024.0f);
        y1 = fminf(fmaxf(y1, 0.0f), 1024.0f);
        x2 = fminf(fmaxf(x2, 0.0f), 1024.0f);
        y2 = fminf(fmaxf(y2, 0.0f), 1024.0f);

        bool valid = (__fsub_rn(x2, x1) >= 1e-3f) && (__fsub_rn(y2, y1) >= 1e-3f);
        g_px[img][pos] = make_float4(x1, y1, x2, y2);
        float sc = valid ? score : -1.0f;
        g_key[img][pos] = ((u64)fkey(sc) << 32) | (u32)(~(u32)pos);

        float ofs = (float)lvl * 1025.0f;
        float ox1 = __fadd_rn(x1, ofs), oy1 = __fadd_rn(y1, ofs);
        float ox2 = __fadd_rn(x2, ofs), oy2 = __fadd_rn(y2, ofs);
        g_lx1[pair][r] = ox1; g_ly1[pair][r] = oy1;
        g_lx2[pair][r] = ox2; g_ly2[pair][r] = oy2;
        g_lar[pair][r] = __fmul_rn(__fsub_rn(ox2, ox1), __fsub_rn(oy2, oy1));
        if (valid) atomicOr(&vb[r >> 6], 1ull << (r & 63));
    }
    __syncthreads();
    if (tid < NWL) g_lvb[pair][tid] = vb[tid];

    // ---- reset per-replay state ----
    if (tid < 256) g_hist[pair][tid] = 0;
    if (tid == 0) g_cntC[pair] = 0;
}

// ================= per-level IoU suppression matrix (upper tri, specialized) ======
#define IOU_BIT(jj)                                                            \
    {                                                                          \
        float ltx = fmaxf(ix1, cx1[jj]);                                       \
        float lty = fmaxf(iy1, cy1[jj]);                                       \
        float rbx = fminf(ix2, cx2[jj]);                                       \
        float rby = fminf(iy2, cy2[jj]);                                       \
        float w = fmaxf(__fsub_rn(rbx, ltx), 0.0f);                            \
        float h = fmaxf(__fsub_rn(rby, lty), 0.0f);                            \
        float inter = __fmul_rn(w, h);                                         \
        float den = __fadd_rn(__fsub_rn(__fadd_rn(ai, car[jj]), inter), 1e-9f);\
        bool sup;                                                              \
        if (inter > __fmul_rn(den, 0.703125f))       sup = true;               \
        else if (inter < __fmul_rn(den, 0.6953125f)) sup = false;              \
        else sup = (__fdiv_rn(inter, den) > 0.7f);                             \
        if (sup) word |= (1ull << (jj));                                       \
    }

__global__ __launch_bounds__(256) void lmask_kernel() {
    int pair = blockIdx.z; int lvl = pair % 5;
    int kl = c_KLVL[lvl];
    int colb = blockIdx.x, rowb4 = blockIdx.y;
    if (rowb4 * 4 > colb) return;            // whole block lower triangle
    int tid = threadIdx.x;
    int sub = tid >> 6, lane = tid & 63;
    int rowb = rowb4 * 4 + sub;

    __shared__ float cx1[64], cy1[64], cx2[64], cy2[64], car[64];
    int j0 = colb * 64;
    if (tid < 64) {
        int j = j0 + tid;
        if (j < kl) {
            cx1[tid] = g_lx1[pair][j]; cy1[tid] = g_ly1[pair][j];
            cx2[tid] = g_lx2[pair][j]; cy2[tid] = g_ly2[pair][j];
            car[tid] = g_lar[pair][j];
        } else {
            cx1[tid] = 0.f; cy1[tid] = 0.f; cx2[tid] = 0.f; cy2[tid] = 0.f; car[tid] = 0.f;
        }
    }
    __syncthreads();
    if (rowb > colb) return;                 // this row-tile below diagonal
    int i = rowb * 64 + lane;
    u64 word = 0ull;
    if (i < kl) {
        float ix1 = g_lx1[pair][i], iy1 = g_ly1[pair][i];
        float ix2 = g_lx2[pair][i], iy2 = g_ly2[pair][i];
        float ai = g_lar[pair][i];
        int jmax = kl - j0; if (jmax > 64) jmax = 64;   // may be <=0 for padded cols
        if (rowb < colb && jmax == 64) {
            // interior tile: every j in-range and j > i — no per-iter conditionals
            #pragma unroll 16
            for (int jj = 0; jj < 64; jj++) IOU_BIT(jj);
        } else if (rowb == colb) {
            // diagonal tile: start at lane+1, bound by jmax
            for (int jj = lane + 1; jj < jmax; jj++) IOU_BIT(jj);
        } else {
            // ragged right edge (rowb < colb, jmax < 64)
            for (int jj = 0; jj < jmax; jj++) IOU_BIT(jj);
        }
    }
    if (i < 1024) g_lmask[pair][i][colb] = word;  // zeros beyond kl keep eager ORs safe
}

// ================= per-level greedy NMS (40 independent blocks) =================
__global__ __launch_bounds__(256) void lnms_kernel() {
    int pair = blockIdx.x; int lvl = pair % 5;
    int kl = c_KLVL[lvl];
    int nc = (kl + 63) >> 6;
    int tid = threadIdx.x;
    __shared__ u64 remv[NWL];
    __shared__ u64 smask[64];
    __shared__ u64 kb[NWL];
    __shared__ int skept[64];
    __shared__ int snk;
    if (tid < NWL) { remv[tid] = 0ull; kb[tid] = 0ull; }
    __syncthreads();

    for (int c = 0; c < nc; c++) {
        int i0 = c * 64;
        if (tid < 64) {
            int i = i0 + tid;
            smask[tid] = (i < kl) ? g_lmask[pair][i][c] : 0ull;
        }
        __syncthreads();
        if (tid == 0) {
            u64 alive = g_lvb[pair][c] & ~remv[c];
            int nk = 0; u64 kw = 0ull;
            while (alive) {
                int b = __ffsll((long long)alive) - 1;
                skept[nk++] = i0 + b; kw |= (1ull << b);
                alive &= ~smask[b];              // row has only j>i bits
                alive &= ~(1ull << b);
            }
            snk = nk; kb[c] = kw;
        }
        __syncthreads();
        int nk = snk, nw = nc - 1 - c;
        int total = nk * nw;
        for (int p = tid; p < total; p += 256) {
            int kk = p / nw; int w = c + 1 + (p - kk * nw);
            u64 mm = g_lmask[pair][skept[kk]][w];
            if (mm) atomicOr(&remv[w], mm);
        }
        __syncthreads();
    }
    if (tid < NWL) g_keepbits[pair][tid] = kb[tid];
}

// ================= rank + merge kept + output (fused, per image) =================
__global__ __launch_bounds__(1024) void rankfin_kernel(float* __restrict__ out) {
    int img = blockIdx.x;
    int tid = threadIdx.x;
    int lane = tid & 31, warp = tid >> 5;

    __shared__ u64 levKeys[KSEL];
    __shared__ u32 sh_wsum[32];
    __shared__ u32 sh_levStart[6];
    __shared__ u32 sh_carry, sh_total;
    __shared__ u64 kbits[NWORDS];
    __shared__ u32 pref[NWORDS + 1];

    for (int t = tid; t < NWORDS; t += 1024) kbits[t] = 0ull;

    u64 key[5]; u32 gvp[5]; bool val[5];
    #pragma unroll
    for (int s = 0; s < 5; s++) {
        int p = s * 1024 + tid;
        key[s] = 0ull; val[s] = false;
        if (p < KSEL) {
            u64 kk = g_key[img][p];
            key[s] = kk;
            val[s] = ((u32)(kk >> 32)) >= 0x80000000u;   // sigmoid>0 vs -1
        }
    }
    if (tid == 0) sh_carry = 0;

    #pragma unroll
    for (int s = 0; s < 5; s++) {
        int p = s * 1024 + tid;
        u32 bal = __ballot_sync(0xFFFFFFFFu, val[s]);
        u32 wpre = __popc(bal & ((1u << lane) - 1u));
        __syncthreads();
        if (lane == 0) sh_wsum[warp] = __popc(bal);
        __syncthreads();
        if (tid < 32) {
            u32 v = sh_wsum[tid];
            u32 x = v;
            #pragma unroll
            for (int o = 1; o < 32; o <<= 1) {
                u32 y = __shfl_up_sync(0xFFFFFFFFu, x, o);
                if (tid >= o) x += y;
            }
            sh_wsum[tid] = x - v;
            if (tid == 31) sh_total = x;
        }
        __syncthreads();
        gvp[s] = sh_carry + sh_wsum[warp] + wpre;
        if (p < KSEL && (p % 1000) == 0 && p < 5000) sh_levStart[p / 1000] = gvp[s];
        __syncthreads();
        if (tid == 0) sh_carry += sh_total;
    }
    __syncthreads();
    if (tid == 0) sh_levStart[5] = sh_carry;
    __syncthreads();

    #pragma unroll
    for (int s = 0; s < 5; s++) {
        int p = s * 1024 + tid;
        if (p < KSEL && val[s]) levKeys[gvp[s]] = key[s];
    }
    __syncthreads();

    u32 rr[5]; bool kt[5];
    #pragma unroll
    for (int s = 0; s < 5; s++) {
        int p = s * 1024 + tid;
        rr[s] = 0; kt[s] = false;
        if (p >= KSEL) continue;
        int lvl = p / 1000; if (lvl > 4) lvl = 4;
        if (val[s]) {
            u32 r = gvp[s] - sh_levStart[lvl];
            #pragma unroll
            for (int l2 = 0; l2 < 5; l2++) {
                if (l2 == lvl) continue;
                u32 lo = sh_levStart[l2], hi = sh_levStart[l2 + 1];
                u32 st = lo;
                while (lo < hi) {
                    u32 mid = (lo + hi) >> 1;
                    if (levKeys[mid] > key[s]) lo = mid + 1; else hi = mid;
                }
                r += lo - st;
            }
            int li = p - c_SELOFF[lvl];
            bool kept = (g_keepbits[img * 5 + lvl][li >> 6] >> (li & 63)) & 1ull;
            if (kept) {
                atomicOr(&kbits[r >> 6], 1ull << (r & 63));
                kt[s] = true;
            }
            rr[s] = r;
        }
    }
    __syncthreads();
    // warp-parallel exclusive prefix over kept-bit popcounts (3 words/lane)
    if (tid < 32) {
        int w0 = tid * 3;
        u32 loc0 = 0, loc1 = 0, loc2 = 0, sum = 0, v;
        if (w0 < NWORDS)     { loc0 = sum; v = (u32)__popcll(kbits[w0]);     sum += v; }
        if (w0 + 1 < NWORDS) { loc1 = sum; v = (u32)__popcll(kbits[w0 + 1]); sum += v; }
        if (w0 + 2 < NWORDS) { loc2 = sum; v = (u32)__popcll(kbits[w0 + 2]); sum += v; }
        u32 x = sum;
        #pragma unroll
        for (int o = 1; o < 32; o <<= 1) {
            u32 y = __shfl_up_sync(0xFFFFFFFFu, x, o);
            if (tid >= o) x += y;
        }
        u32 off = x - sum;
        if (w0 < NWORDS)     pref[w0]     = off + loc0;
        if (w0 + 1 < NWORDS) pref[w0 + 1] = off + loc1;
        if (w0 + 2 < NWORDS) pref[w0 + 2] = off + loc2;
        if (tid == 31) pref[NWORDS] = x;   // total (lanes beyond 24 contribute 0)
    }
    __syncthreads();

    #pragma unroll
    for (int s = 0; s < 5; s++) {
        int p = s * 1024 + tid;
        if (p >= KSEL || !kt[s]) continue;
        u32 r = rr[s];
        u32 low = (r & 63) ? (u32)__popcll(kbits[r >> 6] & ((1ull << (r & 63)) - 1ull)) : 0u;
        u32 orank = pref[r >> 6] + low;
        if (orank < POSTN) {
            float4 b = g_px[img][p];
            float* o = out + ((size_t)img * POSTN + orank) * 4;
            o[0] = b.x; o[1] = b.y; o[2] = b.z; o[3] = b.w;
        }
    }
    int tot = (int)pref[NWORDS]; if (tot > POSTN) tot = POSTN;
    for (int idx = tot * 4 + tid; idx < POSTN * 4; idx += 1024)
        out[(size_t)img * POSTN * 4 + idx] = 0.0f;
}

// ================= host launcher =================
extern "C" void kernel_launch(void* const* d_in, const int* in_sizes, int n_in,
                              void* d_out, int out_size) {
    KArgs A;
    bool interleaved = (in_sizes[1] == 6291456);
    for (int i = 0; i < 5; i++) {
        A.obj[i] = (const float*)d_in[interleaved ? 2 * i : i];
        A.del[i] = (const float*)d_in[interleaved ? 2 * i + 1 : 5 + i];
    }
    A.anc = (const float*)d_in[10];
    float* out = (float*)d_out;

    histA_kernel<<<dim3(40, 16), 256>>>(A);
    compact_kernel<<<dim3(40, 16), 256>>>(A);
    selfin_kernel<<<40, 1024>>>(A);
    lmask_kernel<<<dim3(NWL, 4, 40), 256>>>();
    lnms_kernel<<<40, 256>>>();
    rankfin_kernel<<<NIMG, 1024>>>(out);
}